// round 13
// baseline (speedup 1.0000x reference)
#include <cuda_runtime.h>
#include <cuda_fp16.h>
#include <math.h>
#include <stdint.h>

#define T_TOK 2048
#define HID   1024
#define INTER 512
#define NE    32
#define TOPK  6
#define NGRP  8
#define GSZ   4
#define TKGRP 4
#define NSLOT (T_TOK*TOPK)
#define MAXS  T_TOK
#define SHI   2048

// ---------------- device scratch ----------------
__device__ int   g_cnt[NE];          // zero at load; re-zeroed by combine_k
__device__ int   g_slots[NE*MAXS];
__device__ float g_w[NSLOT];
__device__ __half g_x[T_TOK*HID];
__device__ __half g_upw[NE*INTER*HID];
__device__ __half g_dnw[NE*HID*INTER];
__device__ __half g_shu[SHI*HID];
__device__ __half g_shd[HID*SHI];
__device__ __half g_h[NSLOT*INTER];
__device__ __half g_sh[T_TOK*SHI];
__device__ __half g_partial[(size_t)NSLOT*HID];   // fp16 routed-down partials
__device__ float g_shp0[T_TOK*HID];               // shared-down K-half 0
__device__ float g_shp1[T_TOK*HID];               // shared-down K-half 1

// ---------------- helpers ----------------
static __device__ __forceinline__ uint32_t s2u(const void* p){
    uint32_t a;
    asm("{ .reg .u64 t; cvta.to.shared.u64 t, %1; cvt.u32.u64 %0, t; }"
        : "=r"(a) : "l"(p));
    return a;
}
static __device__ __forceinline__ void cp16(uint32_t dst, const void* src){
    asm volatile("cp.async.cg.shared.global [%0], [%1], 16;"
                 :: "r"(dst), "l"(src));
}
#define CP_COMMIT() asm volatile("cp.async.commit_group;" ::: "memory")

#define LDSM4(r0,r1,r2,r3,a) \
    asm volatile("ldmatrix.sync.aligned.m8n8.x4.shared.b16 {%0,%1,%2,%3}, [%4];" \
                 : "=r"(r0), "=r"(r1), "=r"(r2), "=r"(r3) : "r"(a))

#define MMA16816(d,a,b) \
    asm volatile("mma.sync.aligned.m16n8k16.row.col.f32.f16.f16.f32 " \
                 "{%0,%1,%2,%3},{%4,%5,%6,%7},{%8,%9},{%0,%1,%2,%3};" \
                 : "+f"((d)[0]), "+f"((d)[1]), "+f"((d)[2]), "+f"((d)[3]) \
                 : "r"((a)[0]), "r"((a)[1]), "r"((a)[2]), "r"((a)[3]), \
                   "r"((b)[0]), "r"((b)[1]))

// ---------------------------------------------------------------------------
#define X4  (T_TOK*HID/4)
#define U4  (NE*INTER*HID/4)
#define S4  (SHI*HID/4)
#define D4  (NE*HID*INTER/4)
#define SD4 (HID*SHI/4)
#define CV1 (X4 + U4 + S4)           // launch-0 conv elems (float4)
#define CV1B (CV1 / 256)             // 20480 conv blocks
#define DCV (D4 + SD4)               // down-weight conv elems (in UP launch)
#define NCB (NE * 12 * 16)           // 6144 idle UP cells doing down-conv

static __device__ __forceinline__ void conv4(const float* __restrict__ s,
                                             __half* __restrict__ d, int i){
    float4 v = ((const float4*)s)[i];
    __half2 a = __halves2half2(__float2half_rn(v.x), __float2half_rn(v.y));
    __half2 b = __halves2half2(__float2half_rn(v.z), __float2half_rn(v.w));
    uint2 u; u.x = *(uint32_t*)&a; u.y = *(uint32_t*)&b;
    ((uint2*)d)[i] = u;
}

// ---------------------------------------------------------------------------
// Launch 0: blocks [0,CV1B) convert x/up_w/sh_up_w; blocks [CV1B,+T_TOK)
// run the router (ALU-bound, hides in the DRAM-bound convert).
__global__ __launch_bounds__(256) void conv_router_k(
    const float* __restrict__ x, const float* __restrict__ up,
    const float* __restrict__ su,
    const float* __restrict__ gate_w, const float* __restrict__ e_bias)
{
    const int bx = blockIdx.x;
    if (bx < CV1B) {
        int i = bx * 256 + threadIdx.x;
        if (i < X4)           conv4(x,  g_x,   i);
        else if (i < X4 + U4) conv4(up, g_upw, i - X4);
        else                  conv4(su, g_shu, i - X4 - U4);
        return;
    }
    // ---- router for token t (256 threads) ----
    const int t = bx - CV1B;
    __shared__ float xs[HID];
    __shared__ float logits[NE];

    const float* xr = x + (size_t)t * HID;
    for (int i = threadIdx.x; i < HID / 4; i += 256)
        ((float4*)xs)[i] = ((const float4*)xr)[i];
    __syncthreads();

    int warp = threadIdx.x >> 5, lane = threadIdx.x & 31;
    for (int e = warp * 4; e < warp * 4 + 4; e++) {
        const float* g = gate_w + (size_t)e * HID;
        float p = 0.f;
        #pragma unroll 8
        for (int h = lane; h < HID; h += 32) p += g[h] * xs[h];
        #pragma unroll
        for (int o = 16; o > 0; o >>= 1) p += __shfl_xor_sync(0xffffffffu, p, o);
        if (lane == 0) logits[e] = p;
    }
    __syncthreads();

    if (threadIdx.x == 0) {
        float scores[NE], sc[NE];
        #pragma unroll
        for (int e = 0; e < NE; e++) {
            scores[e] = 1.f / (1.f + expf(-logits[e]));
            sc[e] = scores[e] + e_bias[e];
        }
        float gs[NGRP];
        #pragma unroll
        for (int g = 0; g < NGRP; g++) {
            float m1 = -1e30f, m2 = -1e30f;
            #pragma unroll
            for (int j = 0; j < GSZ; j++) {
                float v = sc[g * GSZ + j];
                if (v > m1) { m2 = m1; m1 = v; }
                else if (v > m2) { m2 = v; }
            }
            gs[g] = m1 + m2;
        }
        bool gsel[NGRP];
        #pragma unroll
        for (int g = 0; g < NGRP; g++) gsel[g] = false;
        for (int r = 0; r < TKGRP; r++) {
            int best = -1; float bv = -1e30f;
            #pragma unroll
            for (int g = 0; g < NGRP; g++)
                if (!gsel[g] && gs[g] > bv) { bv = gs[g]; best = g; }
            gsel[best] = true;
        }
        float masked[NE];
        #pragma unroll
        for (int e = 0; e < NE; e++) masked[e] = gsel[e >> 2] ? sc[e] : 0.0f;
        bool used[NE];
        #pragma unroll
        for (int e = 0; e < NE; e++) used[e] = false;
        int idx[TOPK]; float wv[TOPK]; float wsum = 0.f;
        for (int r = 0; r < TOPK; r++) {
            int best = -1; float bv = -1e30f;
            #pragma unroll
            for (int e = 0; e < NE; e++)
                if (!used[e] && masked[e] > bv) { bv = masked[e]; best = e; }
            used[best] = true;
            idx[r] = best;
            wv[r] = scores[best];
            wsum += wv[r];
        }
        float inv = 2.5f / (wsum + 1e-20f);
        for (int r = 0; r < TOPK; r++) {
            int e = idx[r];
            int s = t * TOPK + r;
            g_w[s] = wv[r] * inv;
            int pos = atomicAdd(&g_cnt[e], 1);
            g_slots[e * MAXS + pos] = s;
        }
    }
}

// ---------------------------------------------------------------------------
// Merged HMMA grouped GEMM — round-7 pipeline (3-stage BK=32, two light
// barriers per chunk, register double-buffered fragments). LJF z ordering.
//   UP:   z==0 shared (x<16, K=1024); z in [1,NE] routed e=z-1 (x<4, K=1024);
//         routed cells with x>=4 are micro conv blocks for down weights
//         (768 float4 each — retire in ~1-2us, no SM squatting).
//   DOWN: z in {0,1} shared K-halves (x<8, K=1024 each, row stride 2048);
//         z in [2,NE+1] routed e=z-2 (x<8, K=512).
#define PITCHB 80u
#define TILEB  (128u*PITCHB)       // 10240 B
#define STGB   (2u*TILEB)
#define SMEM_GEMM (3u*STGB)        // 61440 B

#define LDFRAGS(buf, so, kb) do {                                              \
    _Pragma("unroll")                                                          \
    for (int mt_ = 0; mt_ < 4; mt_++) {                                        \
        uint32_t a_ = (so) + (uint32_t)(wm0 + mt_*16 + aRow) * PITCHB          \
                    + (kb) + aK;                                               \
        LDSM4(av[buf][mt_][0], av[buf][mt_][1],                                \
              av[buf][mt_][2], av[buf][mt_][3], a_);                           \
    }                                                                          \
    _Pragma("unroll")                                                          \
    for (int jp_ = 0; jp_ < 4; jp_ += 2) {                                     \
        uint32_t b_ = (so) + TILEB                                             \
                    + (uint32_t)(wn0 + jp_*8 + bRow) * PITCHB + (kb) + bK;     \
        LDSM4(bv[buf][jp_][0], bv[buf][jp_][1],                                \
              bv[buf][jp_+1][0], bv[buf][jp_+1][1], b_);                       \
    }                                                                          \
} while(0)

#define DOMMA(buf) do {                                                        \
    _Pragma("unroll")                                                          \
    for (int mt_ = 0; mt_ < 4; mt_++)                                          \
        _Pragma("unroll")                                                      \
        for (int jn_ = 0; jn_ < 4; jn_++)                                      \
            MMA16816(acc[mt_][jn_], av[buf][mt_], bv[buf][jn_]);               \
} while(0)

template<bool UP>
__global__ __launch_bounds__(256, 2) void moe_gemm(
    const __half* __restrict__ Ar, const __half* __restrict__ Br,
    const __half* __restrict__ As, const __half* __restrict__ Bs,
    float* __restrict__ Cf0, float* __restrict__ Cf1,
    __half* __restrict__ Chr, __half* __restrict__ Chs,
    int NtR, int KR, int NxR, int NtS, int KS,
    const float* __restrict__ cv1, const float* __restrict__ cv2)
{
    const int z = blockIdx.z;
    const int NSHZ = UP ? 1 : 2;
    const bool sh = (z < NSHZ);
    const int e = sh ? 0 : (z - NSHZ);
    if (!sh && (int)blockIdx.x >= NxR) {
        if (UP) {
            // micro conv block for down weights: fixed 768-float4 chunk
            const int cid = (e * 12 + (blockIdx.x - NxR)) * (int)gridDim.y
                          + blockIdx.y;                       // 0..6143
            for (int i = cid * 256 + threadIdx.x; i < DCV; i += NCB * 256) {
                if (i < D4) conv4(cv1, g_dnw, i);
                else        conv4(cv2, g_shd, i - D4);
            }
        }
        return;
    }
    const int m_count = sh ? T_TOK : g_cnt[e];
    const int m0 = blockIdx.y * 128;
    if (m0 >= m_count) return;
    const int n0 = blockIdx.x * 128;
    const int Kloop = sh ? (UP ? KS : (KS >> 1)) : KR;
    const int Krow  = sh ? KS : KR;
    const int koff  = (sh && !UP) ? z * (KS >> 1) : 0;
    const int Nt = sh ? NtS : NtR;

    extern __shared__ __align__(128) char smem[];
    const uint32_t sb = s2u(smem);
    const int tid = threadIdx.x, wid = tid >> 5, lane = tid & 31;

    // ---- loader: thread pair (2t,2t+1) loads 2x16B of row t ----
    const int lrow = tid >> 1;
    const int lelem = (tid & 1) * 16;
    const int gm = m0 + lrow;
    const int idxr = (gm < m_count) ? gm : 0;
    int arow;
    if (sh) {
        arow = idxr;
    } else {
        int s = g_slots[e * MAXS + idxr];
        arow = UP ? (s / TOPK) : s;
    }
    const __half* pA = (sh ? As : Ar) + (size_t)arow * Krow + koff + lelem;
    const __half* pB = (sh ? Bs : (Br + (size_t)e * NtR * KR))
                       + (size_t)(n0 + lrow) * Krow + koff + lelem;
    const uint32_t ldst = (uint32_t)lrow * PITCHB + (uint32_t)(tid & 1) * 32u;

    const int nk = Kloop >> 5;

    auto load_stage = [&](int k) {
        const uint32_t so = sb + (uint32_t)(k % 3) * STGB + ldst;
        const int k0 = k << 5;
        cp16(so,            pA + k0);
        cp16(so + 16,       pA + k0 + 8);
        cp16(so + TILEB,    pB + k0);
        cp16(so + TILEB+16, pB + k0 + 8);
        CP_COMMIT();
    };

    load_stage(0); load_stage(1); load_stage(2);   // nk >= 16 always

    // ---- compute setup ----
    const int wm0 = (wid & 1) * 64;
    const int wn0 = (wid >> 1) * 32;
    const uint32_t aRow = (uint32_t)(lane & 15);
    const uint32_t aK   = (uint32_t)(lane >> 4) * 16u;
    const uint32_t bRow = (uint32_t)((lane & 7) + ((lane >> 4) & 1) * 8);
    const uint32_t bK   = (uint32_t)((lane >> 3) & 1) * 16u;

    float acc[4][4][4];
    #pragma unroll
    for (int i = 0; i < 4; i++)
        #pragma unroll
        for (int j = 0; j < 4; j++)
            #pragma unroll
            for (int q = 0; q < 4; q++) acc[i][j][q] = 0.f;

    uint32_t av[2][4][4], bv[2][4][2];

    asm volatile("cp.async.wait_group 1;" ::: "memory");
    __syncthreads();
    LDFRAGS(0, sb, 0u);

    for (int k = 0; k < nk; k++) {
        const uint32_t so  = sb + (uint32_t)(k % 3) * STGB;
        const uint32_t son = sb + (uint32_t)((k + 1) % 3) * STGB;
        LDFRAGS(1, so, 32u);
        DOMMA(0);
        if (k + 1 < nk) LDFRAGS(0, son, 0u);
        DOMMA(1);
        __syncthreads();
        if (k + 3 < nk) {
            load_stage(k + 3);
            asm volatile("cp.async.wait_group 1;" ::: "memory");
        } else {
            asm volatile("cp.async.wait_group 0;" ::: "memory");
        }
        __syncthreads();
    }

    // ---- epilogue ----
    const int rw4 = lane >> 2;
    const int cq  = (lane & 3) * 2;
    float* Cfh = (z == 0) ? Cf0 : Cf1;
    #pragma unroll
    for (int mt = 0; mt < 4; mt++) {
        #pragma unroll
        for (int half = 0; half < 2; half++) {
            const int gmi = m0 + wm0 + mt*16 + rw4 + half*8;
            if (gmi >= m_count) continue;
            int crow = gmi; float wsc = 1.f;
            if (!sh) {
                int s = g_slots[e * MAXS + gmi];
                crow = s;
                if (UP) wsc = g_w[s];
            }
            #pragma unroll
            for (int jn = 0; jn < 4; jn++) {
                float v0 = acc[mt][jn][half*2 + 0];
                float v1 = acc[mt][jn][half*2 + 1];
                const int col = n0 + wn0 + jn*8 + cq;
                const size_t off = (size_t)crow * Nt + col;
                if (UP) {
                    v0 = v0 > 0.f ? v0 * v0 : 0.f;
                    v1 = v1 > 0.f ? v1 * v1 : 0.f;
                    v0 *= wsc; v1 *= wsc;
                    __half2 hp = __halves2half2(__float2half_rn(v0),
                                                __float2half_rn(v1));
                    *(uint32_t*)((sh ? Chs : Chr) + off) = *(uint32_t*)&hp;
                } else if (sh) {
                    *(float2*)(Cfh + off) = make_float2(v0, v1);
                } else {
                    __half2 hp = __halves2half2(__float2half_rn(v0),
                                                __float2half_rn(v1));
                    *(uint32_t*)(Chr + off) = *(uint32_t*)&hp;   // g_partial
                }
            }
        }
    }
}

// ---------------------------------------------------------------------------
// out[t] = shp0 + shp1 + sum_{k<6} fp16 g_partial[t*6+k]
// Block 0 re-zeroes g_cnt (globals start zeroed at module load).
__global__ __launch_bounds__(256) void combine_k(float* __restrict__ out) {
    int idx = blockIdx.x * 256 + threadIdx.x;   // float4 index
    int t = idx >> 8;
    int c = idx & 255;
    const float4 p0 = ((const float4*)g_shp0)[idx];
    const float4 p1 = ((const float4*)g_shp1)[idx];
    float4 o = make_float4(p0.x + p1.x, p0.y + p1.y,
                           p0.z + p1.z, p0.w + p1.w);
    #pragma unroll
    for (int k = 0; k < TOPK; k++) {
        uint2 pr = ((const uint2*)g_partial)[(size_t)(t * TOPK + k) * 256 + c];
        __half2 h0 = *(__half2*)&pr.x;
        __half2 h1 = *(__half2*)&pr.y;
        o.x += __low2float(h0);  o.y += __high2float(h0);
        o.z += __low2float(h1);  o.w += __high2float(h1);
    }
    ((float4*)out)[idx] = o;
    if (blockIdx.x == 0 && threadIdx.x < NE) g_cnt[threadIdx.x] = 0;
}

// ---------------------------------------------------------------------------
extern "C" void kernel_launch(void* const* d_in, const int* in_sizes, int n_in,
                              void* d_out, int out_size)
{
    const float* x         = (const float*)d_in[0];
    const float* gate_w    = (const float*)d_in[1];
    const float* e_bias    = (const float*)d_in[2];
    const float* up_w      = (const float*)d_in[3];
    const float* down_w    = (const float*)d_in[4];
    const float* sh_up_w   = (const float*)d_in[5];
    const float* sh_down_w = (const float*)d_in[6];
    float* out = (float*)d_out;

    void *xh, *uw, *dn, *su, *sd, *hb, *shb, *part, *sp0, *sp1;
    cudaGetSymbolAddress(&xh,  g_x);
    cudaGetSymbolAddress(&uw,  g_upw);
    cudaGetSymbolAddress(&dn,  g_dnw);
    cudaGetSymbolAddress(&su,  g_shu);
    cudaGetSymbolAddress(&sd,  g_shd);
    cudaGetSymbolAddress(&hb,  g_h);
    cudaGetSymbolAddress(&shb, g_sh);
    cudaGetSymbolAddress(&part, g_partial);
    cudaGetSymbolAddress(&sp0, g_shp0);
    cudaGetSymbolAddress(&sp1, g_shp1);

    const int smem = (int)SMEM_GEMM;
    cudaFuncSetAttribute(moe_gemm<true>,
                         cudaFuncAttributeMaxDynamicSharedMemorySize, smem);
    cudaFuncSetAttribute(moe_gemm<false>,
                         cudaFuncAttributeMaxDynamicSharedMemorySize, smem);

    // 0: conv (x, up_w, sh_up_w) + router appended
    conv_router_k<<<CV1B + T_TOK, 256>>>(x, up_w, sh_up_w, gate_w, e_bias);

    // 1: UP GEMM — z=0 shared (x<16), z in [1,32] routed (x<4);
    //    idle routed cells (x>=4) micro-convert down weights
    moe_gemm<true><<<dim3(SHI/128, T_TOK/128, NE + 1), 256, smem>>>(
        (const __half*)xh, (const __half*)uw,
        (const __half*)xh, (const __half*)su,
        nullptr, nullptr, (__half*)hb, (__half*)shb,
        INTER, HID, INTER/128, SHI, HID,
        down_w, sh_down_w);

    // 2: DOWN GEMM — z in {0,1} shared K-halves first, z in [2,33] routed
    moe_gemm<false><<<dim3(HID/128, T_TOK/128, NE + 2), 256, smem>>>(
        (const __half*)hb, (const __half*)dn,
        (const __half*)shb, (const __half*)sd,
        (float*)sp0, (float*)sp1, (__half*)part, nullptr,
        HID, INTER, HID/128, HID, SHI,
        nullptr, nullptr);

    // 3: combine (+ re-zero g_cnt)
    combine_k<<<T_TOK, 256>>>(out);
}

// round 14
// speedup vs baseline: 1.0260x; 1.0260x over previous
#include <cuda_runtime.h>
#include <cuda_fp16.h>
#include <math.h>
#include <stdint.h>

#define T_TOK 2048
#define HID   1024
#define INTER 512
#define NE    32
#define TOPK  6
#define NGRP  8
#define GSZ   4
#define TKGRP 4
#define NSLOT (T_TOK*TOPK)
#define MAXS  T_TOK
#define SHI   2048

// ---------------- device scratch ----------------
__device__ int   g_cnt[NE];          // zero at load; re-zeroed by combine_k
__device__ int   g_slots[NE*MAXS];
__device__ float g_w[NSLOT];
__device__ __half g_x[T_TOK*HID];
__device__ __half g_upw[NE*INTER*HID];
__device__ __half g_dnw[NE*HID*INTER];
__device__ __half g_shu[SHI*HID];
__device__ __half g_shd[HID*SHI];
__device__ __half g_h[NSLOT*INTER];
__device__ __half g_sh[T_TOK*SHI];
__device__ __half g_partial[(size_t)NSLOT*HID];   // fp16 routed-down partials
__device__ float g_shp0[T_TOK*HID];               // shared-down K-half 0
__device__ float g_shp1[T_TOK*HID];               // shared-down K-half 1

// ---------------- helpers ----------------
static __device__ __forceinline__ uint32_t s2u(const void* p){
    uint32_t a;
    asm("{ .reg .u64 t; cvta.to.shared.u64 t, %1; cvt.u32.u64 %0, t; }"
        : "=r"(a) : "l"(p));
    return a;
}
static __device__ __forceinline__ void cp16(uint32_t dst, const void* src){
    asm volatile("cp.async.cg.shared.global [%0], [%1], 16;"
                 :: "r"(dst), "l"(src));
}
#define CP_COMMIT() asm volatile("cp.async.commit_group;" ::: "memory")

#define LDSM4(r0,r1,r2,r3,a) \
    asm volatile("ldmatrix.sync.aligned.m8n8.x4.shared.b16 {%0,%1,%2,%3}, [%4];" \
                 : "=r"(r0), "=r"(r1), "=r"(r2), "=r"(r3) : "r"(a))

#define MMA16816(d,a,b) \
    asm volatile("mma.sync.aligned.m16n8k16.row.col.f32.f16.f16.f32 " \
                 "{%0,%1,%2,%3},{%4,%5,%6,%7},{%8,%9},{%0,%1,%2,%3};" \
                 : "+f"((d)[0]), "+f"((d)[1]), "+f"((d)[2]), "+f"((d)[3]) \
                 : "r"((a)[0]), "r"((a)[1]), "r"((a)[2]), "r"((a)[3]), \
                   "r"((b)[0]), "r"((b)[1]))

// ---------------------------------------------------------------------------
#define X4  (T_TOK*HID/4)
#define U4  (NE*INTER*HID/4)
#define S4  (SHI*HID/4)
#define D4  (NE*HID*INTER/4)
#define SD4 (HID*SHI/4)
#define CV1 (X4 + U4 + S4)           // launch-0 conv elems (float4)
#define DCV (D4 + SD4)               // down-weight conv elems (in UP launch)
#define NCB (NE * 12 * 16)           // 6144 idle UP cells doing down-conv

static __device__ __forceinline__ void conv4(const float* __restrict__ s,
                                             __half* __restrict__ d, int i){
    float4 v = ((const float4*)s)[i];
    __half2 a = __halves2half2(__float2half_rn(v.x), __float2half_rn(v.y));
    __half2 b = __halves2half2(__float2half_rn(v.z), __float2half_rn(v.w));
    uint2 u; u.x = *(uint32_t*)&a; u.y = *(uint32_t*)&b;
    ((uint2*)d)[i] = u;
}

// Launch 0: plain low-register convert of x, up_w, sh_up_w.
__global__ __launch_bounds__(256) void conv1_k(
    const float* __restrict__ x, const float* __restrict__ up,
    const float* __restrict__ su)
{
    int i = blockIdx.x * 256 + threadIdx.x;
    if (i < X4)           conv4(x,  g_x,   i);
    else if (i < X4 + U4) conv4(up, g_upw, i - X4);
    else                  conv4(su, g_shu, i - X4 - U4);
}

// ---------------------------------------------------------------------------
// Router: one block per token, 128 threads. fp32-exact (validated round 1).
__global__ __launch_bounds__(128) void router_k(
    const float* __restrict__ x,
    const float* __restrict__ gate_w,
    const float* __restrict__ e_bias)
{
    int t = blockIdx.x;
    __shared__ float xs[HID];
    __shared__ float logits[NE];

    const float* xr = x + (size_t)t * HID;
    for (int i = threadIdx.x; i < HID / 4; i += 128)
        ((float4*)xs)[i] = ((const float4*)xr)[i];
    __syncthreads();

    int warp = threadIdx.x >> 5, lane = threadIdx.x & 31;
    for (int e = warp * 8; e < warp * 8 + 8; e++) {
        const float* g = gate_w + (size_t)e * HID;
        float p = 0.f;
        #pragma unroll 8
        for (int h = lane; h < HID; h += 32) p += g[h] * xs[h];
        #pragma unroll
        for (int o = 16; o > 0; o >>= 1) p += __shfl_xor_sync(0xffffffffu, p, o);
        if (lane == 0) logits[e] = p;
    }
    __syncthreads();

    if (threadIdx.x == 0) {
        float scores[NE], sc[NE];
        #pragma unroll
        for (int e = 0; e < NE; e++) {
            scores[e] = 1.f / (1.f + expf(-logits[e]));
            sc[e] = scores[e] + e_bias[e];
        }
        float gs[NGRP];
        #pragma unroll
        for (int g = 0; g < NGRP; g++) {
            float m1 = -1e30f, m2 = -1e30f;
            #pragma unroll
            for (int j = 0; j < GSZ; j++) {
                float v = sc[g * GSZ + j];
                if (v > m1) { m2 = m1; m1 = v; }
                else if (v > m2) { m2 = v; }
            }
            gs[g] = m1 + m2;
        }
        bool gsel[NGRP];
        #pragma unroll
        for (int g = 0; g < NGRP; g++) gsel[g] = false;
        for (int r = 0; r < TKGRP; r++) {
            int best = -1; float bv = -1e30f;
            #pragma unroll
            for (int g = 0; g < NGRP; g++)
                if (!gsel[g] && gs[g] > bv) { bv = gs[g]; best = g; }
            gsel[best] = true;
        }
        float masked[NE];
        #pragma unroll
        for (int e = 0; e < NE; e++) masked[e] = gsel[e >> 2] ? sc[e] : 0.0f;
        bool used[NE];
        #pragma unroll
        for (int e = 0; e < NE; e++) used[e] = false;
        int idx[TOPK]; float wv[TOPK]; float wsum = 0.f;
        for (int r = 0; r < TOPK; r++) {
            int best = -1; float bv = -1e30f;
            #pragma unroll
            for (int e = 0; e < NE; e++)
                if (!used[e] && masked[e] > bv) { bv = masked[e]; best = e; }
            used[best] = true;
            idx[r] = best;
            wv[r] = scores[best];
            wsum += wv[r];
        }
        float inv = 2.5f / (wsum + 1e-20f);
        for (int r = 0; r < TOPK; r++) {
            int e = idx[r];
            int s = t * TOPK + r;
            g_w[s] = wv[r] * inv;
            int pos = atomicAdd(&g_cnt[e], 1);
            g_slots[e * MAXS + pos] = s;
        }
    }
}

// ---------------------------------------------------------------------------
// Merged HMMA grouped GEMM — round-7 pipeline (3-stage BK=32, two light
// barriers per chunk, register double-buffered fragments). LJF z ordering.
//   UP:   z==0 shared (x<16, K=1024); z in [1,NE] routed e=z-1 (x<4, K=1024);
//         routed cells with x>=4 micro-convert down weights (fast-retiring).
//   DOWN: z in {0,1} shared K-halves (x<8, K=1024 each, row stride 2048);
//         z in [2,NE+1] routed e=z-2 (x<8, K=512).
#define PITCHB 80u
#define TILEB  (128u*PITCHB)       // 10240 B
#define STGB   (2u*TILEB)
#define SMEM_GEMM (3u*STGB)        // 61440 B

#define LDFRAGS(buf, so, kb) do {                                              \
    _Pragma("unroll")                                                          \
    for (int mt_ = 0; mt_ < 4; mt_++) {                                        \
        uint32_t a_ = (so) + (uint32_t)(wm0 + mt_*16 + aRow) * PITCHB          \
                    + (kb) + aK;                                               \
        LDSM4(av[buf][mt_][0], av[buf][mt_][1],                                \
              av[buf][mt_][2], av[buf][mt_][3], a_);                           \
    }                                                                          \
    _Pragma("unroll")                                                          \
    for (int jp_ = 0; jp_ < 4; jp_ += 2) {                                     \
        uint32_t b_ = (so) + TILEB                                             \
                    + (uint32_t)(wn0 + jp_*8 + bRow) * PITCHB + (kb) + bK;     \
        LDSM4(bv[buf][jp_][0], bv[buf][jp_][1],                                \
              bv[buf][jp_+1][0], bv[buf][jp_+1][1], b_);                       \
    }                                                                          \
} while(0)

#define DOMMA(buf) do {                                                        \
    _Pragma("unroll")                                                          \
    for (int mt_ = 0; mt_ < 4; mt_++)                                          \
        _Pragma("unroll")                                                      \
        for (int jn_ = 0; jn_ < 4; jn_++)                                      \
            MMA16816(acc[mt_][jn_], av[buf][mt_], bv[buf][jn_]);               \
} while(0)

template<bool UP>
__global__ __launch_bounds__(256, 2) void moe_gemm(
    const __half* __restrict__ Ar, const __half* __restrict__ Br,
    const __half* __restrict__ As, const __half* __restrict__ Bs,
    float* __restrict__ Cf0, float* __restrict__ Cf1,
    __half* __restrict__ Chr, __half* __restrict__ Chs,
    int NtR, int KR, int NxR, int NtS, int KS,
    const float* __restrict__ cv1, const float* __restrict__ cv2)
{
    const int z = blockIdx.z;
    const int NSHZ = UP ? 1 : 2;
    const bool sh = (z < NSHZ);
    const int e = sh ? 0 : (z - NSHZ);
    if (!sh && (int)blockIdx.x >= NxR) {
        if (UP) {
            // micro conv block for down weights: ~3x256 float4 per block
            const int cid = (e * 12 + (blockIdx.x - NxR)) * (int)gridDim.y
                          + blockIdx.y;                       // 0..6143
            for (int i = cid * 256 + threadIdx.x; i < DCV; i += NCB * 256) {
                if (i < D4) conv4(cv1, g_dnw, i);
                else        conv4(cv2, g_shd, i - D4);
            }
        }
        return;
    }
    const int m_count = sh ? T_TOK : g_cnt[e];
    const int m0 = blockIdx.y * 128;
    if (m0 >= m_count) return;
    const int n0 = blockIdx.x * 128;
    const int Kloop = sh ? (UP ? KS : (KS >> 1)) : KR;
    const int Krow  = sh ? KS : KR;
    const int koff  = (sh && !UP) ? z * (KS >> 1) : 0;
    const int Nt = sh ? NtS : NtR;

    extern __shared__ __align__(128) char smem[];
    const uint32_t sb = s2u(smem);
    const int tid = threadIdx.x, wid = tid >> 5, lane = tid & 31;

    // ---- loader: thread pair (2t,2t+1) loads 2x16B of row t ----
    const int lrow = tid >> 1;
    const int lelem = (tid & 1) * 16;
    const int gm = m0 + lrow;
    const int idxr = (gm < m_count) ? gm : 0;
    int arow;
    if (sh) {
        arow = idxr;
    } else {
        int s = g_slots[e * MAXS + idxr];
        arow = UP ? (s / TOPK) : s;
    }
    const __half* pA = (sh ? As : Ar) + (size_t)arow * Krow + koff + lelem;
    const __half* pB = (sh ? Bs : (Br + (size_t)e * NtR * KR))
                       + (size_t)(n0 + lrow) * Krow + koff + lelem;
    const uint32_t ldst = (uint32_t)lrow * PITCHB + (uint32_t)(tid & 1) * 32u;

    const int nk = Kloop >> 5;

    auto load_stage = [&](int k) {
        const uint32_t so = sb + (uint32_t)(k % 3) * STGB + ldst;
        const int k0 = k << 5;
        cp16(so,            pA + k0);
        cp16(so + 16,       pA + k0 + 8);
        cp16(so + TILEB,    pB + k0);
        cp16(so + TILEB+16, pB + k0 + 8);
        CP_COMMIT();
    };

    load_stage(0); load_stage(1); load_stage(2);   // nk >= 16 always

    // ---- compute setup ----
    const int wm0 = (wid & 1) * 64;
    const int wn0 = (wid >> 1) * 32;
    const uint32_t aRow = (uint32_t)(lane & 15);
    const uint32_t aK   = (uint32_t)(lane >> 4) * 16u;
    const uint32_t bRow = (uint32_t)((lane & 7) + ((lane >> 4) & 1) * 8);
    const uint32_t bK   = (uint32_t)((lane >> 3) & 1) * 16u;

    float acc[4][4][4];
    #pragma unroll
    for (int i = 0; i < 4; i++)
        #pragma unroll
        for (int j = 0; j < 4; j++)
            #pragma unroll
            for (int q = 0; q < 4; q++) acc[i][j][q] = 0.f;

    uint32_t av[2][4][4], bv[2][4][2];

    asm volatile("cp.async.wait_group 1;" ::: "memory");
    __syncthreads();
    LDFRAGS(0, sb, 0u);

    for (int k = 0; k < nk; k++) {
        const uint32_t so  = sb + (uint32_t)(k % 3) * STGB;
        const uint32_t son = sb + (uint32_t)((k + 1) % 3) * STGB;
        LDFRAGS(1, so, 32u);
        DOMMA(0);
        if (k + 1 < nk) LDFRAGS(0, son, 0u);
        DOMMA(1);
        __syncthreads();
        if (k + 3 < nk) {
            load_stage(k + 3);
            asm volatile("cp.async.wait_group 1;" ::: "memory");
        } else {
            asm volatile("cp.async.wait_group 0;" ::: "memory");
        }
        __syncthreads();
    }

    // ---- epilogue ----
    const int rw4 = lane >> 2;
    const int cq  = (lane & 3) * 2;
    float* Cfh = (z == 0) ? Cf0 : Cf1;
    #pragma unroll
    for (int mt = 0; mt < 4; mt++) {
        #pragma unroll
        for (int half = 0; half < 2; half++) {
            const int gmi = m0 + wm0 + mt*16 + rw4 + half*8;
            if (gmi >= m_count) continue;
            int crow = gmi; float wsc = 1.f;
            if (!sh) {
                int s = g_slots[e * MAXS + gmi];
                crow = s;
                if (UP) wsc = g_w[s];
            }
            #pragma unroll
            for (int jn = 0; jn < 4; jn++) {
                float v0 = acc[mt][jn][half*2 + 0];
                float v1 = acc[mt][jn][half*2 + 1];
                const int col = n0 + wn0 + jn*8 + cq;
                const size_t off = (size_t)crow * Nt + col;
                if (UP) {
                    v0 = v0 > 0.f ? v0 * v0 : 0.f;
                    v1 = v1 > 0.f ? v1 * v1 : 0.f;
                    v0 *= wsc; v1 *= wsc;
                    __half2 hp = __halves2half2(__float2half_rn(v0),
                                                __float2half_rn(v1));
                    *(uint32_t*)((sh ? Chs : Chr) + off) = *(uint32_t*)&hp;
                } else if (sh) {
                    *(float2*)(Cfh + off) = make_float2(v0, v1);
                } else {
                    __half2 hp = __halves2half2(__float2half_rn(v0),
                                                __float2half_rn(v1));
                    *(uint32_t*)(Chr + off) = *(uint32_t*)&hp;   // g_partial
                }
            }
        }
    }
}

// ---------------------------------------------------------------------------
// out[t] = shp0 + shp1 + sum_{k<6} fp16 g_partial[t*6+k]
// Block 0 re-zeroes g_cnt (globals start zeroed at module load).
__global__ __launch_bounds__(256) void combine_k(float* __restrict__ out) {
    int idx = blockIdx.x * 256 + threadIdx.x;   // float4 index
    int t = idx >> 8;
    int c = idx & 255;
    const float4 p0 = ((const float4*)g_shp0)[idx];
    const float4 p1 = ((const float4*)g_shp1)[idx];
    float4 o = make_float4(p0.x + p1.x, p0.y + p1.y,
                           p0.z + p1.z, p0.w + p1.w);
    #pragma unroll
    for (int k = 0; k < TOPK; k++) {
        uint2 pr = ((const uint2*)g_partial)[(size_t)(t * TOPK + k) * 256 + c];
        __half2 h0 = *(__half2*)&pr.x;
        __half2 h1 = *(__half2*)&pr.y;
        o.x += __low2float(h0);  o.y += __high2float(h0);
        o.z += __low2float(h1);  o.w += __high2float(h1);
    }
    ((float4*)out)[idx] = o;
    if (blockIdx.x == 0 && threadIdx.x < NE) g_cnt[threadIdx.x] = 0;
}

// ---------------------------------------------------------------------------
extern "C" void kernel_launch(void* const* d_in, const int* in_sizes, int n_in,
                              void* d_out, int out_size)
{
    const float* x         = (const float*)d_in[0];
    const float* gate_w    = (const float*)d_in[1];
    const float* e_bias    = (const float*)d_in[2];
    const float* up_w      = (const float*)d_in[3];
    const float* down_w    = (const float*)d_in[4];
    const float* sh_up_w   = (const float*)d_in[5];
    const float* sh_down_w = (const float*)d_in[6];
    float* out = (float*)d_out;

    void *xh, *uw, *dn, *su, *sd, *hb, *shb, *part, *sp0, *sp1;
    cudaGetSymbolAddress(&xh,  g_x);
    cudaGetSymbolAddress(&uw,  g_upw);
    cudaGetSymbolAddress(&dn,  g_dnw);
    cudaGetSymbolAddress(&su,  g_shu);
    cudaGetSymbolAddress(&sd,  g_shd);
    cudaGetSymbolAddress(&hb,  g_h);
    cudaGetSymbolAddress(&shb, g_sh);
    cudaGetSymbolAddress(&part, g_partial);
    cudaGetSymbolAddress(&sp0, g_shp0);
    cudaGetSymbolAddress(&sp1, g_shp1);

    const int smem = (int)SMEM_GEMM;
    cudaFuncSetAttribute(moe_gemm<true>,
                         cudaFuncAttributeMaxDynamicSharedMemorySize, smem);
    cudaFuncSetAttribute(moe_gemm<false>,
                         cudaFuncAttributeMaxDynamicSharedMemorySize, smem);

    // 0: low-register convert of x, up_w, sh_up_w
    conv1_k<<<CV1 / 256, 256>>>(x, up_w, sh_up_w);
    // 1: router (separate launch — keeps conv kernel registers low)
    router_k<<<T_TOK, 128>>>(x, gate_w, e_bias);

    // 2: UP GEMM — z=0 shared (x<16), z in [1,32] routed (x<4);
    //    idle routed cells (x>=4) micro-convert down weights
    moe_gemm<true><<<dim3(SHI/128, T_TOK/128, NE + 1), 256, smem>>>(
        (const __half*)xh, (const __half*)uw,
        (const __half*)xh, (const __half*)su,
        nullptr, nullptr, (__half*)hb, (__half*)shb,
        INTER, HID, INTER/128, SHI, HID,
        down_w, sh_down_w);

    // 3: DOWN GEMM — z in {0,1} shared K-halves first, z in [2,33] routed
    moe_gemm<false><<<dim3(HID/128, T_TOK/128, NE + 2), 256, smem>>>(
        (const __half*)hb, (const __half*)dn,
        (const __half*)shb, (const __half*)sd,
        (float*)sp0, (float*)sp1, (__half*)part, nullptr,
        HID, INTER, HID/128, HID, SHI,
        nullptr, nullptr);

    // 4: combine (+ re-zero g_cnt)
    combine_k<<<T_TOK, 256>>>(out);
}

// round 15
// speedup vs baseline: 1.1101x; 1.0819x over previous
#include <cuda_runtime.h>
#include <cuda_fp16.h>
#include <math.h>
#include <stdint.h>

#define T_TOK 2048
#define HID   1024
#define INTER 512
#define NE    32
#define TOPK  6
#define NGRP  8
#define GSZ   4
#define TKGRP 4
#define NSLOT (T_TOK*TOPK)
#define MAXS  T_TOK
#define SHI   2048

// ---------------- device scratch ----------------
__device__ int   g_cnt[NE];          // zero at load; re-zeroed by combine_k
__device__ int   g_slots[NE*MAXS];
__device__ float g_w[NSLOT];
__device__ __half g_x[T_TOK*HID];
__device__ __half g_upw[NE*INTER*HID];
__device__ __half g_dnw[NE*HID*INTER];
__device__ __half g_shu[SHI*HID];
__device__ __half g_shd[HID*SHI];
__device__ __half g_h[NSLOT*INTER];
__device__ __half g_sh[T_TOK*SHI];
__device__ __half g_partial[(size_t)NSLOT*HID];   // fp16 routed-down partials
__device__ float g_shp0[T_TOK*HID];               // shared-down K-half 0
__device__ float g_shp1[T_TOK*HID];               // shared-down K-half 1

// ---------------- helpers ----------------
static __device__ __forceinline__ uint32_t s2u(const void* p){
    uint32_t a;
    asm("{ .reg .u64 t; cvta.to.shared.u64 t, %1; cvt.u32.u64 %0, t; }"
        : "=r"(a) : "l"(p));
    return a;
}
static __device__ __forceinline__ void cp16(uint32_t dst, const void* src){
    asm volatile("cp.async.cg.shared.global [%0], [%1], 16;"
                 :: "r"(dst), "l"(src));
}
#define CP_COMMIT() asm volatile("cp.async.commit_group;" ::: "memory")

#define LDSM4(r0,r1,r2,r3,a) \
    asm volatile("ldmatrix.sync.aligned.m8n8.x4.shared.b16 {%0,%1,%2,%3}, [%4];" \
                 : "=r"(r0), "=r"(r1), "=r"(r2), "=r"(r3) : "r"(a))

#define MMA16816(d,a,b) \
    asm volatile("mma.sync.aligned.m16n8k16.row.col.f32.f16.f16.f32 " \
                 "{%0,%1,%2,%3},{%4,%5,%6,%7},{%8,%9},{%0,%1,%2,%3};" \
                 : "+f"((d)[0]), "+f"((d)[1]), "+f"((d)[2]), "+f"((d)[3]) \
                 : "r"((a)[0]), "r"((a)[1]), "r"((a)[2]), "r"((a)[3]), \
                   "r"((b)[0]), "r"((b)[1]))

// ---------------------------------------------------------------------------
// Single merged fp32->fp16 convert over all 5 tensors (grid-stride, MLP=2).
#define X4  (T_TOK*HID/4)
#define U4  (NE*INTER*HID/4)
#define S4  (SHI*HID/4)
#define D4  (NE*HID*INTER/4)
#define SD4 (HID*SHI/4)
#define CV_TOT (X4 + U4 + S4 + D4 + SD4)

static __device__ __forceinline__ void conv4(const float* __restrict__ s,
                                             __half* __restrict__ d, int i){
    float4 v = ((const float4*)s)[i];
    __half2 a = __halves2half2(__float2half_rn(v.x), __float2half_rn(v.y));
    __half2 b = __halves2half2(__float2half_rn(v.z), __float2half_rn(v.w));
    uint2 u; u.x = *(uint32_t*)&a; u.y = *(uint32_t*)&b;
    ((uint2*)d)[i] = u;
}

static __device__ __forceinline__ void conv_route(
    const float* __restrict__ x,  const float* __restrict__ up,
    const float* __restrict__ su, const float* __restrict__ dn,
    const float* __restrict__ sd, int i)
{
    int j = i;
    if (j < X4)  { conv4(x,  g_x,   j); return; }  j -= X4;
    if (j < U4)  { conv4(up, g_upw, j); return; }  j -= U4;
    if (j < S4)  { conv4(su, g_shu, j); return; }  j -= S4;
    if (j < D4)  { conv4(dn, g_dnw, j); return; }  j -= D4;
    conv4(sd, g_shd, j);
}

__global__ __launch_bounds__(256) void conv_all_k(
    const float* __restrict__ x,  const float* __restrict__ up,
    const float* __restrict__ su, const float* __restrict__ dn,
    const float* __restrict__ sd)
{
    const int stride = gridDim.x * 256;
    int i = blockIdx.x * 256 + threadIdx.x;
    // unrolled pairs: two independent loads in flight per thread (MLP=2)
    for (; i + stride < CV_TOT; i += 2 * stride) {
        conv_route(x, up, su, dn, sd, i);
        conv_route(x, up, su, dn, sd, i + stride);
    }
    if (i < CV_TOT) conv_route(x, up, su, dn, sd, i);
}

// ---------------------------------------------------------------------------
// Router: one block per token, 128 threads. fp32-exact (validated round 1).
__global__ __launch_bounds__(128) void router_k(
    const float* __restrict__ x,
    const float* __restrict__ gate_w,
    const float* __restrict__ e_bias)
{
    int t = blockIdx.x;
    __shared__ float xs[HID];
    __shared__ float logits[NE];

    const float* xr = x + (size_t)t * HID;
    for (int i = threadIdx.x; i < HID / 4; i += 128)
        ((float4*)xs)[i] = ((const float4*)xr)[i];
    __syncthreads();

    int warp = threadIdx.x >> 5, lane = threadIdx.x & 31;
    for (int e = warp * 8; e < warp * 8 + 8; e++) {
        const float* g = gate_w + (size_t)e * HID;
        float p = 0.f;
        #pragma unroll 8
        for (int h = lane; h < HID; h += 32) p += g[h] * xs[h];
        #pragma unroll
        for (int o = 16; o > 0; o >>= 1) p += __shfl_xor_sync(0xffffffffu, p, o);
        if (lane == 0) logits[e] = p;
    }
    __syncthreads();

    if (threadIdx.x == 0) {
        float scores[NE], sc[NE];
        #pragma unroll
        for (int e = 0; e < NE; e++) {
            scores[e] = 1.f / (1.f + expf(-logits[e]));
            sc[e] = scores[e] + e_bias[e];
        }
        float gs[NGRP];
        #pragma unroll
        for (int g = 0; g < NGRP; g++) {
            float m1 = -1e30f, m2 = -1e30f;
            #pragma unroll
            for (int j = 0; j < GSZ; j++) {
                float v = sc[g * GSZ + j];
                if (v > m1) { m2 = m1; m1 = v; }
                else if (v > m2) { m2 = v; }
            }
            gs[g] = m1 + m2;
        }
        bool gsel[NGRP];
        #pragma unroll
        for (int g = 0; g < NGRP; g++) gsel[g] = false;
        for (int r = 0; r < TKGRP; r++) {
            int best = -1; float bv = -1e30f;
            #pragma unroll
            for (int g = 0; g < NGRP; g++)
                if (!gsel[g] && gs[g] > bv) { bv = gs[g]; best = g; }
            gsel[best] = true;
        }
        float masked[NE];
        #pragma unroll
        for (int e = 0; e < NE; e++) masked[e] = gsel[e >> 2] ? sc[e] : 0.0f;
        bool used[NE];
        #pragma unroll
        for (int e = 0; e < NE; e++) used[e] = false;
        int idx[TOPK]; float wv[TOPK]; float wsum = 0.f;
        for (int r = 0; r < TOPK; r++) {
            int best = -1; float bv = -1e30f;
            #pragma unroll
            for (int e = 0; e < NE; e++)
                if (!used[e] && masked[e] > bv) { bv = masked[e]; best = e; }
            used[best] = true;
            idx[r] = best;
            wv[r] = scores[best];
            wsum += wv[r];
        }
        float inv = 2.5f / (wsum + 1e-20f);
        for (int r = 0; r < TOPK; r++) {
            int e = idx[r];
            int s = t * TOPK + r;
            g_w[s] = wv[r] * inv;
            int pos = atomicAdd(&g_cnt[e], 1);
            g_slots[e * MAXS + pos] = s;
        }
    }
}

// ---------------------------------------------------------------------------
// Merged HMMA grouped GEMM — round-7 pipeline (3-stage BK=32, two light
// barriers per chunk, register double-buffered fragments). LJF z ordering.
//   UP:   z==0 shared (x<16, K=1024); z in [1,NE] routed e=z-1 (x<4, K=1024)
//   DOWN: z in {0,1} shared K-halves (x<8, K=1024 each, row stride 2048);
//         z in [2,NE+1] routed e=z-2 (x<8, K=512)
#define PITCHB 80u
#define TILEB  (128u*PITCHB)       // 10240 B
#define STGB   (2u*TILEB)
#define SMEM_GEMM (3u*STGB)        // 61440 B

#define LDFRAGS(buf, so, kb) do {                                              \
    _Pragma("unroll")                                                          \
    for (int mt_ = 0; mt_ < 4; mt_++) {                                        \
        uint32_t a_ = (so) + (uint32_t)(wm0 + mt_*16 + aRow) * PITCHB          \
                    + (kb) + aK;                                               \
        LDSM4(av[buf][mt_][0], av[buf][mt_][1],                                \
              av[buf][mt_][2], av[buf][mt_][3], a_);                           \
    }                                                                          \
    _Pragma("unroll")                                                          \
    for (int jp_ = 0; jp_ < 4; jp_ += 2) {                                     \
        uint32_t b_ = (so) + TILEB                                             \
                    + (uint32_t)(wn0 + jp_*8 + bRow) * PITCHB + (kb) + bK;     \
        LDSM4(bv[buf][jp_][0], bv[buf][jp_][1],                                \
              bv[buf][jp_+1][0], bv[buf][jp_+1][1], b_);                       \
    }                                                                          \
} while(0)

#define DOMMA(buf) do {                                                        \
    _Pragma("unroll")                                                          \
    for (int mt_ = 0; mt_ < 4; mt_++)                                          \
        _Pragma("unroll")                                                      \
        for (int jn_ = 0; jn_ < 4; jn_++)                                      \
            MMA16816(acc[mt_][jn_], av[buf][mt_], bv[buf][jn_]);               \
} while(0)

template<bool UP>
__global__ __launch_bounds__(256, 2) void moe_gemm(
    const __half* __restrict__ Ar, const __half* __restrict__ Br,
    const __half* __restrict__ As, const __half* __restrict__ Bs,
    float* __restrict__ Cf0, float* __restrict__ Cf1,
    __half* __restrict__ Chr, __half* __restrict__ Chs,
    int NtR, int KR, int NxR, int NtS, int KS)
{
    const int z = blockIdx.z;
    const int NSHZ = UP ? 1 : 2;
    const bool sh = (z < NSHZ);
    const int e = sh ? 0 : (z - NSHZ);
    if (!sh && (int)blockIdx.x >= NxR) return;
    const int m_count = sh ? T_TOK : g_cnt[e];
    const int m0 = blockIdx.y * 128;
    if (m0 >= m_count) return;
    const int n0 = blockIdx.x * 128;
    const int Kloop = sh ? (UP ? KS : (KS >> 1)) : KR;
    const int Krow  = sh ? KS : KR;
    const int koff  = (sh && !UP) ? z * (KS >> 1) : 0;
    const int Nt = sh ? NtS : NtR;

    extern __shared__ __align__(128) char smem[];
    const uint32_t sb = s2u(smem);
    const int tid = threadIdx.x, wid = tid >> 5, lane = tid & 31;

    // ---- loader: thread pair (2t,2t+1) loads 2x16B of row t ----
    const int lrow = tid >> 1;
    const int lelem = (tid & 1) * 16;
    const int gm = m0 + lrow;
    const int idxr = (gm < m_count) ? gm : 0;
    int arow;
    if (sh) {
        arow = idxr;
    } else {
        int s = g_slots[e * MAXS + idxr];
        arow = UP ? (s / TOPK) : s;
    }
    const __half* pA = (sh ? As : Ar) + (size_t)arow * Krow + koff + lelem;
    const __half* pB = (sh ? Bs : (Br + (size_t)e * NtR * KR))
                       + (size_t)(n0 + lrow) * Krow + koff + lelem;
    const uint32_t ldst = (uint32_t)lrow * PITCHB + (uint32_t)(tid & 1) * 32u;

    const int nk = Kloop >> 5;

    auto load_stage = [&](int k) {
        const uint32_t so = sb + (uint32_t)(k % 3) * STGB + ldst;
        const int k0 = k << 5;
        cp16(so,            pA + k0);
        cp16(so + 16,       pA + k0 + 8);
        cp16(so + TILEB,    pB + k0);
        cp16(so + TILEB+16, pB + k0 + 8);
        CP_COMMIT();
    };

    load_stage(0); load_stage(1); load_stage(2);   // nk >= 16 always

    // ---- compute setup ----
    const int wm0 = (wid & 1) * 64;
    const int wn0 = (wid >> 1) * 32;
    const uint32_t aRow = (uint32_t)(lane & 15);
    const uint32_t aK   = (uint32_t)(lane >> 4) * 16u;
    const uint32_t bRow = (uint32_t)((lane & 7) + ((lane >> 4) & 1) * 8);
    const uint32_t bK   = (uint32_t)((lane >> 3) & 1) * 16u;

    float acc[4][4][4];
    #pragma unroll
    for (int i = 0; i < 4; i++)
        #pragma unroll
        for (int j = 0; j < 4; j++)
            #pragma unroll
            for (int q = 0; q < 4; q++) acc[i][j][q] = 0.f;

    uint32_t av[2][4][4], bv[2][4][2];

    asm volatile("cp.async.wait_group 1;" ::: "memory");
    __syncthreads();
    LDFRAGS(0, sb, 0u);

    for (int k = 0; k < nk; k++) {
        const uint32_t so  = sb + (uint32_t)(k % 3) * STGB;
        const uint32_t son = sb + (uint32_t)((k + 1) % 3) * STGB;
        LDFRAGS(1, so, 32u);
        DOMMA(0);
        if (k + 1 < nk) LDFRAGS(0, son, 0u);
        DOMMA(1);
        __syncthreads();
        if (k + 3 < nk) {
            load_stage(k + 3);
            asm volatile("cp.async.wait_group 1;" ::: "memory");
        } else {
            asm volatile("cp.async.wait_group 0;" ::: "memory");
        }
        __syncthreads();
    }

    // ---- epilogue ----
    const int rw4 = lane >> 2;
    const int cq  = (lane & 3) * 2;
    float* Cfh = (z == 0) ? Cf0 : Cf1;
    #pragma unroll
    for (int mt = 0; mt < 4; mt++) {
        #pragma unroll
        for (int half = 0; half < 2; half++) {
            const int gmi = m0 + wm0 + mt*16 + rw4 + half*8;
            if (gmi >= m_count) continue;
            int crow = gmi; float wsc = 1.f;
            if (!sh) {
                int s = g_slots[e * MAXS + gmi];
                crow = s;
                if (UP) wsc = g_w[s];
            }
            #pragma unroll
            for (int jn = 0; jn < 4; jn++) {
                float v0 = acc[mt][jn][half*2 + 0];
                float v1 = acc[mt][jn][half*2 + 1];
                const int col = n0 + wn0 + jn*8 + cq;
                const size_t off = (size_t)crow * Nt + col;
                if (UP) {
                    v0 = v0 > 0.f ? v0 * v0 : 0.f;
                    v1 = v1 > 0.f ? v1 * v1 : 0.f;
                    v0 *= wsc; v1 *= wsc;
                    __half2 hp = __halves2half2(__float2half_rn(v0),
                                                __float2half_rn(v1));
                    *(uint32_t*)((sh ? Chs : Chr) + off) = *(uint32_t*)&hp;
                } else if (sh) {
                    *(float2*)(Cfh + off) = make_float2(v0, v1);
                } else {
                    __half2 hp = __halves2half2(__float2half_rn(v0),
                                                __float2half_rn(v1));
                    *(uint32_t*)(Chr + off) = *(uint32_t*)&hp;   // g_partial
                }
            }
        }
    }
}

// ---------------------------------------------------------------------------
// out[t] = shp0 + shp1 + sum_{k<6} fp16 g_partial[t*6+k]
// Block 0 re-zeroes g_cnt (globals start zeroed at module load).
__global__ __launch_bounds__(256) void combine_k(float* __restrict__ out) {
    int idx = blockIdx.x * 256 + threadIdx.x;   // float4 index
    int t = idx >> 8;
    int c = idx & 255;
    const float4 p0 = ((const float4*)g_shp0)[idx];
    const float4 p1 = ((const float4*)g_shp1)[idx];
    float4 o = make_float4(p0.x + p1.x, p0.y + p1.y,
                           p0.z + p1.z, p0.w + p1.w);
    #pragma unroll
    for (int k = 0; k < TOPK; k++) {
        uint2 pr = ((const uint2*)g_partial)[(size_t)(t * TOPK + k) * 256 + c];
        __half2 h0 = *(__half2*)&pr.x;
        __half2 h1 = *(__half2*)&pr.y;
        o.x += __low2float(h0);  o.y += __high2float(h0);
        o.z += __low2float(h1);  o.w += __high2float(h1);
    }
    ((float4*)out)[idx] = o;
    if (blockIdx.x == 0 && threadIdx.x < NE) g_cnt[threadIdx.x] = 0;
}

// ---------------------------------------------------------------------------
extern "C" void kernel_launch(void* const* d_in, const int* in_sizes, int n_in,
                              void* d_out, int out_size)
{
    const float* x         = (const float*)d_in[0];
    const float* gate_w    = (const float*)d_in[1];
    const float* e_bias    = (const float*)d_in[2];
    const float* up_w      = (const float*)d_in[3];
    const float* down_w    = (const float*)d_in[4];
    const float* sh_up_w   = (const float*)d_in[5];
    const float* sh_down_w = (const float*)d_in[6];
    float* out = (float*)d_out;

    void *xh, *uw, *dn, *su, *sd, *hb, *shb, *part, *sp0, *sp1;
    cudaGetSymbolAddress(&xh,  g_x);
    cudaGetSymbolAddress(&uw,  g_upw);
    cudaGetSymbolAddress(&dn,  g_dnw);
    cudaGetSymbolAddress(&su,  g_shu);
    cudaGetSymbolAddress(&sd,  g_shd);
    cudaGetSymbolAddress(&hb,  g_h);
    cudaGetSymbolAddress(&shb, g_sh);
    cudaGetSymbolAddress(&part, g_partial);
    cudaGetSymbolAddress(&sp0, g_shp0);
    cudaGetSymbolAddress(&sp1, g_shp1);

    const int smem = (int)SMEM_GEMM;
    cudaFuncSetAttribute(moe_gemm<true>,
                         cudaFuncAttributeMaxDynamicSharedMemorySize, smem);
    cudaFuncSetAttribute(moe_gemm<false>,
                         cudaFuncAttributeMaxDynamicSharedMemorySize, smem);

    // 0: merged converts (all 5 tensors, grid-stride, MLP=2)
    conv_all_k<<<12288, 256>>>(x, up_w, sh_up_w, down_w, sh_down_w);
    // 1: router
    router_k<<<T_TOK, 128>>>(x, gate_w, e_bias);

    // 2: UP GEMM — z=0 shared (x<16), z in [1,32] routed (x<4)
    moe_gemm<true><<<dim3(SHI/128, T_TOK/128, NE + 1), 256, smem>>>(
        (const __half*)xh, (const __half*)uw,
        (const __half*)xh, (const __half*)su,
        nullptr, nullptr, (__half*)hb, (__half*)shb,
        INTER, HID, INTER/128, SHI, HID);

    // 3: DOWN GEMM — z in {0,1} shared K-halves first, z in [2,33] routed
    moe_gemm<false><<<dim3(HID/128, T_TOK/128, NE + 2), 256, smem>>>(
        (const __half*)hb, (const __half*)dn,
        (const __half*)shb, (const __half*)sd,
        (float*)sp0, (float*)sp1, (__half*)part, nullptr,
        HID, INTER, HID/128, HID, SHI);

    // 4: combine (+ re-zero g_cnt)
    combine_k<<<T_TOK, 256>>>(out);
}

// round 16
// speedup vs baseline: 1.1210x; 1.0098x over previous
#include <cuda_runtime.h>
#include <cuda_fp16.h>
#include <math.h>
#include <stdint.h>

#define T_TOK 2048
#define HID   1024
#define INTER 512
#define NE    32
#define TOPK  6
#define NGRP  8
#define GSZ   4
#define TKGRP 4
#define NSLOT (T_TOK*TOPK)
#define MAXS  T_TOK
#define SHI   2048

// ---------------- device scratch ----------------
__device__ int   g_cnt[NE];          // zero at load; re-zeroed by combine_k
__device__ int   g_slots[NE*MAXS];
__device__ float g_w[NSLOT];
__device__ __half g_x[T_TOK*HID];
__device__ __half g_upw[NE*INTER*HID];
__device__ __half g_dnw[NE*HID*INTER];
__device__ __half g_shu[SHI*HID];
__device__ __half g_shd[HID*SHI];
__device__ __half g_h[NSLOT*INTER];
__device__ __half g_sh[T_TOK*SHI];
__device__ __half g_partial[(size_t)NSLOT*HID];   // fp16 routed-down partials
__device__ float g_shp0[T_TOK*HID];               // shared-down K-half 0
__device__ float g_shp1[T_TOK*HID];               // shared-down K-half 1

// ---------------- helpers ----------------
static __device__ __forceinline__ uint32_t s2u(const void* p){
    uint32_t a;
    asm("{ .reg .u64 t; cvta.to.shared.u64 t, %1; cvt.u32.u64 %0, t; }"
        : "=r"(a) : "l"(p));
    return a;
}
static __device__ __forceinline__ void cp16(uint32_t dst, const void* src){
    asm volatile("cp.async.cg.shared.global [%0], [%1], 16;"
                 :: "r"(dst), "l"(src));
}
#define CP_COMMIT() asm volatile("cp.async.commit_group;" ::: "memory")

#define LDSM4(r0,r1,r2,r3,a) \
    asm volatile("ldmatrix.sync.aligned.m8n8.x4.shared.b16 {%0,%1,%2,%3}, [%4];" \
                 : "=r"(r0), "=r"(r1), "=r"(r2), "=r"(r3) : "r"(a))

#define MMA16816(d,a,b) \
    asm volatile("mma.sync.aligned.m16n8k16.row.col.f32.f16.f16.f32 " \
                 "{%0,%1,%2,%3},{%4,%5,%6,%7},{%8,%9},{%0,%1,%2,%3};" \
                 : "+f"((d)[0]), "+f"((d)[1]), "+f"((d)[2]), "+f"((d)[3]) \
                 : "r"((a)[0]), "r"((a)[1]), "r"((a)[2]), "r"((a)[3]), \
                   "r"((b)[0]), "r"((b)[1]))

// ---------------------------------------------------------------------------
// Merged fp32->fp16 convert over all 5 tensors.
// 8 floats per thread: two independent float4 loads (MLP=2) -> one uint4 store.
// All tensor sizes are even in float4 units, so an oct never straddles tensors.
#define X4  (T_TOK*HID/4)
#define U4  (NE*INTER*HID/4)
#define S4  (SHI*HID/4)
#define D4  (NE*HID*INTER/4)
#define SD4 (HID*SHI/4)
#define CV_TOT (X4 + U4 + S4 + D4 + SD4)
#define CV_OCT (CV_TOT / 2)

static __device__ __forceinline__ void conv8(const float* __restrict__ s,
                                             __half* __restrict__ d, int o){
    const float4* sp = (const float4*)s + 2 * (size_t)o;
    float4 v0 = sp[0];
    float4 v1 = sp[1];
    __half2 a0 = __floats2half2_rn(v0.x, v0.y);
    __half2 a1 = __floats2half2_rn(v0.z, v0.w);
    __half2 a2 = __floats2half2_rn(v1.x, v1.y);
    __half2 a3 = __floats2half2_rn(v1.z, v1.w);
    uint4 u;
    u.x = *(uint32_t*)&a0; u.y = *(uint32_t*)&a1;
    u.z = *(uint32_t*)&a2; u.w = *(uint32_t*)&a3;
    ((uint4*)d)[o] = u;
}

__global__ __launch_bounds__(256) void conv_all_k(
    const float* __restrict__ x,  const float* __restrict__ up,
    const float* __restrict__ su, const float* __restrict__ dn,
    const float* __restrict__ sd)
{
    int i = blockIdx.x * 256 + threadIdx.x;   // oct index (8 floats)
    if (i >= CV_OCT) return;
    int j = i;
    if (j < X4/2)  { conv8(x,  g_x,   j); return; }  j -= X4/2;
    if (j < U4/2)  { conv8(up, g_upw, j); return; }  j -= U4/2;
    if (j < S4/2)  { conv8(su, g_shu, j); return; }  j -= S4/2;
    if (j < D4/2)  { conv8(dn, g_dnw, j); return; }  j -= D4/2;
    conv8(sd, g_shd, j);
}

// ---------------------------------------------------------------------------
// Router: one block per token, 128 threads. fp32-exact (validated round 1).
__global__ __launch_bounds__(128) void router_k(
    const float* __restrict__ x,
    const float* __restrict__ gate_w,
    const float* __restrict__ e_bias)
{
    int t = blockIdx.x;
    __shared__ float xs[HID];
    __shared__ float logits[NE];

    const float* xr = x + (size_t)t * HID;
    for (int i = threadIdx.x; i < HID / 4; i += 128)
        ((float4*)xs)[i] = ((const float4*)xr)[i];
    __syncthreads();

    int warp = threadIdx.x >> 5, lane = threadIdx.x & 31;
    for (int e = warp * 8; e < warp * 8 + 8; e++) {
        const float* g = gate_w + (size_t)e * HID;
        float p = 0.f;
        #pragma unroll 8
        for (int h = lane; h < HID; h += 32) p += g[h] * xs[h];
        #pragma unroll
        for (int o = 16; o > 0; o >>= 1) p += __shfl_xor_sync(0xffffffffu, p, o);
        if (lane == 0) logits[e] = p;
    }
    __syncthreads();

    if (threadIdx.x == 0) {
        float scores[NE], sc[NE];
        #pragma unroll
        for (int e = 0; e < NE; e++) {
            scores[e] = 1.f / (1.f + expf(-logits[e]));
            sc[e] = scores[e] + e_bias[e];
        }
        float gs[NGRP];
        #pragma unroll
        for (int g = 0; g < NGRP; g++) {
            float m1 = -1e30f, m2 = -1e30f;
            #pragma unroll
            for (int j = 0; j < GSZ; j++) {
                float v = sc[g * GSZ + j];
                if (v > m1) { m2 = m1; m1 = v; }
                else if (v > m2) { m2 = v; }
            }
            gs[g] = m1 + m2;
        }
        bool gsel[NGRP];
        #pragma unroll
        for (int g = 0; g < NGRP; g++) gsel[g] = false;
        for (int r = 0; r < TKGRP; r++) {
            int best = -1; float bv = -1e30f;
            #pragma unroll
            for (int g = 0; g < NGRP; g++)
                if (!gsel[g] && gs[g] > bv) { bv = gs[g]; best = g; }
            gsel[best] = true;
        }
        float masked[NE];
        #pragma unroll
        for (int e = 0; e < NE; e++) masked[e] = gsel[e >> 2] ? sc[e] : 0.0f;
        bool used[NE];
        #pragma unroll
        for (int e = 0; e < NE; e++) used[e] = false;
        int idx[TOPK]; float wv[TOPK]; float wsum = 0.f;
        for (int r = 0; r < TOPK; r++) {
            int best = -1; float bv = -1e30f;
            #pragma unroll
            for (int e = 0; e < NE; e++)
                if (!used[e] && masked[e] > bv) { bv = masked[e]; best = e; }
            used[best] = true;
            idx[r] = best;
            wv[r] = scores[best];
            wsum += wv[r];
        }
        float inv = 2.5f / (wsum + 1e-20f);
        for (int r = 0; r < TOPK; r++) {
            int e = idx[r];
            int s = t * TOPK + r;
            g_w[s] = wv[r] * inv;
            int pos = atomicAdd(&g_cnt[e], 1);
            g_slots[e * MAXS + pos] = s;
        }
    }
}

// ---------------------------------------------------------------------------
// Merged HMMA grouped GEMM — round-7 pipeline (3-stage BK=32, two light
// barriers per chunk, register double-buffered fragments). LJF z ordering.
//   UP:   z==0 shared (x<16, K=1024); z in [1,NE] routed e=z-1 (x<4, K=1024)
//   DOWN: z in {0,1} shared K-halves (x<8, K=1024 each, row stride 2048);
//         z in [2,NE+1] routed e=z-2 (x<8, K=512)
#define PITCHB 80u
#define TILEB  (128u*PITCHB)       // 10240 B
#define STGB   (2u*TILEB)
#define SMEM_GEMM (3u*STGB)        // 61440 B

#define LDFRAGS(buf, so, kb) do {                                              \
    _Pragma("unroll")                                                          \
    for (int mt_ = 0; mt_ < 4; mt_++) {                                        \
        uint32_t a_ = (so) + (uint32_t)(wm0 + mt_*16 + aRow) * PITCHB          \
                    + (kb) + aK;                                               \
        LDSM4(av[buf][mt_][0], av[buf][mt_][1],                                \
              av[buf][mt_][2], av[buf][mt_][3], a_);                           \
    }                                                                          \
    _Pragma("unroll")                                                          \
    for (int jp_ = 0; jp_ < 4; jp_ += 2) {                                     \
        uint32_t b_ = (so) + TILEB                                             \
                    + (uint32_t)(wn0 + jp_*8 + bRow) * PITCHB + (kb) + bK;     \
        LDSM4(bv[buf][jp_][0], bv[buf][jp_][1],                                \
              bv[buf][jp_+1][0], bv[buf][jp_+1][1], b_);                       \
    }                                                                          \
} while(0)

#define DOMMA(buf) do {                                                        \
    _Pragma("unroll")                                                          \
    for (int mt_ = 0; mt_ < 4; mt_++)                                          \
        _Pragma("unroll")                                                      \
        for (int jn_ = 0; jn_ < 4; jn_++)                                      \
            MMA16816(acc[mt_][jn_], av[buf][mt_], bv[buf][jn_]);               \
} while(0)

template<bool UP>
__global__ __launch_bounds__(256, 2) void moe_gemm(
    const __half* __restrict__ Ar, const __half* __restrict__ Br,
    const __half* __restrict__ As, const __half* __restrict__ Bs,
    float* __restrict__ Cf0, float* __restrict__ Cf1,
    __half* __restrict__ Chr, __half* __restrict__ Chs,
    int NtR, int KR, int NxR, int NtS, int KS)
{
    const int z = blockIdx.z;
    const int NSHZ = UP ? 1 : 2;
    const bool sh = (z < NSHZ);
    const int e = sh ? 0 : (z - NSHZ);
    if (!sh && (int)blockIdx.x >= NxR) return;
    const int m_count = sh ? T_TOK : g_cnt[e];
    const int m0 = blockIdx.y * 128;
    if (m0 >= m_count) return;
    const int n0 = blockIdx.x * 128;
    const int Kloop = sh ? (UP ? KS : (KS >> 1)) : KR;
    const int Krow  = sh ? KS : KR;
    const int koff  = (sh && !UP) ? z * (KS >> 1) : 0;
    const int Nt = sh ? NtS : NtR;

    extern __shared__ __align__(128) char smem[];
    const uint32_t sb = s2u(smem);
    const int tid = threadIdx.x, wid = tid >> 5, lane = tid & 31;

    // ---- loader: thread pair (2t,2t+1) loads 2x16B of row t ----
    const int lrow = tid >> 1;
    const int lelem = (tid & 1) * 16;
    const int gm = m0 + lrow;
    const int idxr = (gm < m_count) ? gm : 0;
    int arow;
    if (sh) {
        arow = idxr;
    } else {
        int s = g_slots[e * MAXS + idxr];
        arow = UP ? (s / TOPK) : s;
    }
    const __half* pA = (sh ? As : Ar) + (size_t)arow * Krow + koff + lelem;
    const __half* pB = (sh ? Bs : (Br + (size_t)e * NtR * KR))
                       + (size_t)(n0 + lrow) * Krow + koff + lelem;
    const uint32_t ldst = (uint32_t)lrow * PITCHB + (uint32_t)(tid & 1) * 32u;

    const int nk = Kloop >> 5;

    auto load_stage = [&](int k) {
        const uint32_t so = sb + (uint32_t)(k % 3) * STGB + ldst;
        const int k0 = k << 5;
        cp16(so,            pA + k0);
        cp16(so + 16,       pA + k0 + 8);
        cp16(so + TILEB,    pB + k0);
        cp16(so + TILEB+16, pB + k0 + 8);
        CP_COMMIT();
    };

    load_stage(0); load_stage(1); load_stage(2);   // nk >= 16 always

    // ---- compute setup ----
    const int wm0 = (wid & 1) * 64;
    const int wn0 = (wid >> 1) * 32;
    const uint32_t aRow = (uint32_t)(lane & 15);
    const uint32_t aK   = (uint32_t)(lane >> 4) * 16u;
    const uint32_t bRow = (uint32_t)((lane & 7) + ((lane >> 4) & 1) * 8);
    const uint32_t bK   = (uint32_t)((lane >> 3) & 1) * 16u;

    float acc[4][4][4];
    #pragma unroll
    for (int i = 0; i < 4; i++)
        #pragma unroll
        for (int j = 0; j < 4; j++)
            #pragma unroll
            for (int q = 0; q < 4; q++) acc[i][j][q] = 0.f;

    uint32_t av[2][4][4], bv[2][4][2];

    asm volatile("cp.async.wait_group 1;" ::: "memory");
    __syncthreads();
    LDFRAGS(0, sb, 0u);

    for (int k = 0; k < nk; k++) {
        const uint32_t so  = sb + (uint32_t)(k % 3) * STGB;
        const uint32_t son = sb + (uint32_t)((k + 1) % 3) * STGB;
        LDFRAGS(1, so, 32u);
        DOMMA(0);
        if (k + 1 < nk) LDFRAGS(0, son, 0u);
        DOMMA(1);
        __syncthreads();
        if (k + 3 < nk) {
            load_stage(k + 3);
            asm volatile("cp.async.wait_group 1;" ::: "memory");
        } else {
            asm volatile("cp.async.wait_group 0;" ::: "memory");
        }
        __syncthreads();
    }

    // ---- epilogue ----
    const int rw4 = lane >> 2;
    const int cq  = (lane & 3) * 2;
    float* Cfh = (z == 0) ? Cf0 : Cf1;
    #pragma unroll
    for (int mt = 0; mt < 4; mt++) {
        #pragma unroll
        for (int half = 0; half < 2; half++) {
            const int gmi = m0 + wm0 + mt*16 + rw4 + half*8;
            if (gmi >= m_count) continue;
            int crow = gmi; float wsc = 1.f;
            if (!sh) {
                int s = g_slots[e * MAXS + gmi];
                crow = s;
                if (UP) wsc = g_w[s];
            }
            #pragma unroll
            for (int jn = 0; jn < 4; jn++) {
                float v0 = acc[mt][jn][half*2 + 0];
                float v1 = acc[mt][jn][half*2 + 1];
                const int col = n0 + wn0 + jn*8 + cq;
                const size_t off = (size_t)crow * Nt + col;
                if (UP) {
                    v0 = v0 > 0.f ? v0 * v0 : 0.f;
                    v1 = v1 > 0.f ? v1 * v1 : 0.f;
                    v0 *= wsc; v1 *= wsc;
                    __half2 hp = __halves2half2(__float2half_rn(v0),
                                                __float2half_rn(v1));
                    *(uint32_t*)((sh ? Chs : Chr) + off) = *(uint32_t*)&hp;
                } else if (sh) {
                    *(float2*)(Cfh + off) = make_float2(v0, v1);
                } else {
                    __half2 hp = __halves2half2(__float2half_rn(v0),
                                                __float2half_rn(v1));
                    *(uint32_t*)(Chr + off) = *(uint32_t*)&hp;   // g_partial
                }
            }
        }
    }
}

// ---------------------------------------------------------------------------
// out[t] = shp0 + shp1 + sum_{k<6} fp16 g_partial[t*6+k]
// Block 0 re-zeroes g_cnt (globals start zeroed at module load).
__global__ __launch_bounds__(256) void combine_k(float* __restrict__ out) {
    int idx = blockIdx.x * 256 + threadIdx.x;   // float4 index
    int t = idx >> 8;
    int c = idx & 255;
    const float4 p0 = ((const float4*)g_shp0)[idx];
    const float4 p1 = ((const float4*)g_shp1)[idx];
    float4 o = make_float4(p0.x + p1.x, p0.y + p1.y,
                           p0.z + p1.z, p0.w + p1.w);
    #pragma unroll
    for (int k = 0; k < TOPK; k++) {
        uint2 pr = ((const uint2*)g_partial)[(size_t)(t * TOPK + k) * 256 + c];
        __half2 h0 = *(__half2*)&pr.x;
        __half2 h1 = *(__half2*)&pr.y;
        o.x += __low2float(h0);  o.y += __high2float(h0);
        o.z += __low2float(h1);  o.w += __high2float(h1);
    }
    ((float4*)out)[idx] = o;
    if (blockIdx.x == 0 && threadIdx.x < NE) g_cnt[threadIdx.x] = 0;
}

// ---------------------------------------------------------------------------
extern "C" void kernel_launch(void* const* d_in, const int* in_sizes, int n_in,
                              void* d_out, int out_size)
{
    const float* x         = (const float*)d_in[0];
    const float* gate_w    = (const float*)d_in[1];
    const float* e_bias    = (const float*)d_in[2];
    const float* up_w      = (const float*)d_in[3];
    const float* down_w    = (const float*)d_in[4];
    const float* sh_up_w   = (const float*)d_in[5];
    const float* sh_down_w = (const float*)d_in[6];
    float* out = (float*)d_out;

    void *xh, *uw, *dn, *su, *sd, *hb, *shb, *part, *sp0, *sp1;
    cudaGetSymbolAddress(&xh,  g_x);
    cudaGetSymbolAddress(&uw,  g_upw);
    cudaGetSymbolAddress(&dn,  g_dnw);
    cudaGetSymbolAddress(&su,  g_shu);
    cudaGetSymbolAddress(&sd,  g_shd);
    cudaGetSymbolAddress(&hb,  g_h);
    cudaGetSymbolAddress(&shb, g_sh);
    cudaGetSymbolAddress(&part, g_partial);
    cudaGetSymbolAddress(&sp0, g_shp0);
    cudaGetSymbolAddress(&sp1, g_shp1);

    const int smem = (int)SMEM_GEMM;
    cudaFuncSetAttribute(moe_gemm<true>,
                         cudaFuncAttributeMaxDynamicSharedMemorySize, smem);
    cudaFuncSetAttribute(moe_gemm<false>,
                         cudaFuncAttributeMaxDynamicSharedMemorySize, smem);

    // 0: merged converts (all 5 tensors, 8 floats/thread, uint4 stores)
    conv_all_k<<<(CV_OCT + 255) / 256, 256>>>(x, up_w, sh_up_w,
                                              down_w, sh_down_w);
    // 1: router
    router_k<<<T_TOK, 128>>>(x, gate_w, e_bias);

    // 2: UP GEMM — z=0 shared (x<16), z in [1,32] routed (x<4)
    moe_gemm<true><<<dim3(SHI/128, T_TOK/128, NE + 1), 256, smem>>>(
        (const __half*)xh, (const __half*)uw,
        (const __half*)xh, (const __half*)su,
        nullptr, nullptr, (__half*)hb, (__half*)shb,
        INTER, HID, INTER/128, SHI, HID);

    // 3: DOWN GEMM — z in {0,1} shared K-halves first, z in [2,33] routed
    moe_gemm<false><<<dim3(HID/128, T_TOK/128, NE + 2), 256, smem>>>(
        (const __half*)hb, (const __half*)dn,
        (const __half*)shb, (const __half*)sd,
        (float*)sp0, (float*)sp1, (__half*)part, nullptr,
        HID, INTER, HID/128, HID, SHI);

    // 4: combine (+ re-zero g_cnt)
    combine_k<<<T_TOK, 256>>>(out);
}

// round 17
// speedup vs baseline: 1.1283x; 1.0065x over previous
#include <cuda_runtime.h>
#include <cuda_fp16.h>
#include <math.h>
#include <stdint.h>

#define T_TOK 2048
#define HID   1024
#define INTER 512
#define NE    32
#define TOPK  6
#define NGRP  8
#define GSZ   4
#define TKGRP 4
#define NSLOT (T_TOK*TOPK)
#define MAXS  T_TOK
#define SHI   2048

// ---------------- device scratch ----------------
__device__ int   g_cnt[NE];          // zero at load; re-zeroed by combine_k
__device__ int   g_slots[NE*MAXS];
__device__ float g_w[NSLOT];
__device__ __half g_x[T_TOK*HID];
__device__ __half g_upw[NE*INTER*HID];
__device__ __half g_dnw[NE*HID*INTER];
__device__ __half g_shu[SHI*HID];
__device__ __half g_shd[HID*SHI];
__device__ __half g_h[NSLOT*INTER];
__device__ __half g_sh[T_TOK*SHI];
__device__ __half g_partial[(size_t)NSLOT*HID];   // fp16 routed-down partials
__device__ __half g_shp0[T_TOK*HID];              // shared-down K-half 0 (fp16)
__device__ __half g_shp1[T_TOK*HID];              // shared-down K-half 1 (fp16)

// ---------------- helpers ----------------
static __device__ __forceinline__ uint32_t s2u(const void* p){
    uint32_t a;
    asm("{ .reg .u64 t; cvta.to.shared.u64 t, %1; cvt.u32.u64 %0, t; }"
        : "=r"(a) : "l"(p));
    return a;
}
static __device__ __forceinline__ void cp16(uint32_t dst, const void* src){
    asm volatile("cp.async.cg.shared.global [%0], [%1], 16;"
                 :: "r"(dst), "l"(src));
}
#define CP_COMMIT() asm volatile("cp.async.commit_group;" ::: "memory")

#define LDSM4(r0,r1,r2,r3,a) \
    asm volatile("ldmatrix.sync.aligned.m8n8.x4.shared.b16 {%0,%1,%2,%3}, [%4];" \
                 : "=r"(r0), "=r"(r1), "=r"(r2), "=r"(r3) : "r"(a))

#define MMA16816(d,a,b) \
    asm volatile("mma.sync.aligned.m16n8k16.row.col.f32.f16.f16.f32 " \
                 "{%0,%1,%2,%3},{%4,%5,%6,%7},{%8,%9},{%0,%1,%2,%3};" \
                 : "+f"((d)[0]), "+f"((d)[1]), "+f"((d)[2]), "+f"((d)[3]) \
                 : "r"((a)[0]), "r"((a)[1]), "r"((a)[2]), "r"((a)[3]), \
                   "r"((b)[0]), "r"((b)[1]))

// ---------------------------------------------------------------------------
// Merged fp32->fp16 convert over all 5 tensors.
// 8 floats per thread: two independent float4 loads (MLP=2) -> one uint4 store.
#define X4  (T_TOK*HID/4)
#define U4  (NE*INTER*HID/4)
#define S4  (SHI*HID/4)
#define D4  (NE*HID*INTER/4)
#define SD4 (HID*SHI/4)
#define CV_TOT (X4 + U4 + S4 + D4 + SD4)
#define CV_OCT (CV_TOT / 2)

static __device__ __forceinline__ void conv8(const float* __restrict__ s,
                                             __half* __restrict__ d, int o){
    const float4* sp = (const float4*)s + 2 * (size_t)o;
    float4 v0 = sp[0];
    float4 v1 = sp[1];
    __half2 a0 = __floats2half2_rn(v0.x, v0.y);
    __half2 a1 = __floats2half2_rn(v0.z, v0.w);
    __half2 a2 = __floats2half2_rn(v1.x, v1.y);
    __half2 a3 = __floats2half2_rn(v1.z, v1.w);
    uint4 u;
    u.x = *(uint32_t*)&a0; u.y = *(uint32_t*)&a1;
    u.z = *(uint32_t*)&a2; u.w = *(uint32_t*)&a3;
    ((uint4*)d)[o] = u;
}

__global__ __launch_bounds__(256) void conv_all_k(
    const float* __restrict__ x,  const float* __restrict__ up,
    const float* __restrict__ su, const float* __restrict__ dn,
    const float* __restrict__ sd)
{
    int i = blockIdx.x * 256 + threadIdx.x;   // oct index (8 floats)
    if (i >= CV_OCT) return;
    int j = i;
    if (j < X4/2)  { conv8(x,  g_x,   j); return; }  j -= X4/2;
    if (j < U4/2)  { conv8(up, g_upw, j); return; }  j -= U4/2;
    if (j < S4/2)  { conv8(su, g_shu, j); return; }  j -= S4/2;
    if (j < D4/2)  { conv8(dn, g_dnw, j); return; }  j -= D4/2;
    conv8(sd, g_shd, j);
}

// ---------------------------------------------------------------------------
// Router: one block per token, 128 threads. fp32-exact (validated round 1).
__global__ __launch_bounds__(128) void router_k(
    const float* __restrict__ x,
    const float* __restrict__ gate_w,
    const float* __restrict__ e_bias)
{
    int t = blockIdx.x;
    __shared__ float xs[HID];
    __shared__ float logits[NE];

    const float* xr = x + (size_t)t * HID;
    for (int i = threadIdx.x; i < HID / 4; i += 128)
        ((float4*)xs)[i] = ((const float4*)xr)[i];
    __syncthreads();

    int warp = threadIdx.x >> 5, lane = threadIdx.x & 31;
    for (int e = warp * 8; e < warp * 8 + 8; e++) {
        const float* g = gate_w + (size_t)e * HID;
        float p = 0.f;
        #pragma unroll 8
        for (int h = lane; h < HID; h += 32) p += g[h] * xs[h];
        #pragma unroll
        for (int o = 16; o > 0; o >>= 1) p += __shfl_xor_sync(0xffffffffu, p, o);
        if (lane == 0) logits[e] = p;
    }
    __syncthreads();

    if (threadIdx.x == 0) {
        float scores[NE], sc[NE];
        #pragma unroll
        for (int e = 0; e < NE; e++) {
            scores[e] = 1.f / (1.f + expf(-logits[e]));
            sc[e] = scores[e] + e_bias[e];
        }
        float gs[NGRP];
        #pragma unroll
        for (int g = 0; g < NGRP; g++) {
            float m1 = -1e30f, m2 = -1e30f;
            #pragma unroll
            for (int j = 0; j < GSZ; j++) {
                float v = sc[g * GSZ + j];
                if (v > m1) { m2 = m1; m1 = v; }
                else if (v > m2) { m2 = v; }
            }
            gs[g] = m1 + m2;
        }
        bool gsel[NGRP];
        #pragma unroll
        for (int g = 0; g < NGRP; g++) gsel[g] = false;
        for (int r = 0; r < TKGRP; r++) {
            int best = -1; float bv = -1e30f;
            #pragma unroll
            for (int g = 0; g < NGRP; g++)
                if (!gsel[g] && gs[g] > bv) { bv = gs[g]; best = g; }
            gsel[best] = true;
        }
        float masked[NE];
        #pragma unroll
        for (int e = 0; e < NE; e++) masked[e] = gsel[e >> 2] ? sc[e] : 0.0f;
        bool used[NE];
        #pragma unroll
        for (int e = 0; e < NE; e++) used[e] = false;
        int idx[TOPK]; float wv[TOPK]; float wsum = 0.f;
        for (int r = 0; r < TOPK; r++) {
            int best = -1; float bv = -1e30f;
            #pragma unroll
            for (int e = 0; e < NE; e++)
                if (!used[e] && masked[e] > bv) { bv = masked[e]; best = e; }
            used[best] = true;
            idx[r] = best;
            wv[r] = scores[best];
            wsum += wv[r];
        }
        float inv = 2.5f / (wsum + 1e-20f);
        for (int r = 0; r < TOPK; r++) {
            int e = idx[r];
            int s = t * TOPK + r;
            g_w[s] = wv[r] * inv;
            int pos = atomicAdd(&g_cnt[e], 1);
            g_slots[e * MAXS + pos] = s;
        }
    }
}

// ---------------------------------------------------------------------------
// Merged HMMA grouped GEMM — round-7 pipeline (3-stage BK=32, two light
// barriers per chunk, register double-buffered fragments). LJF z ordering.
//   UP:   z==0 shared (x<16, K=1024); z in [1,NE] routed e=z-1 (x<4, K=1024)
//   DOWN: z in {0,1} shared K-halves (x<8, K=1024 each, row stride 2048);
//         z in [2,NE+1] routed e=z-2 (x<8, K=512)
// All outputs fp16 now (routed partials, shared halves, h, sh).
#define PITCHB 80u
#define TILEB  (128u*PITCHB)       // 10240 B
#define STGB   (2u*TILEB)
#define SMEM_GEMM (3u*STGB)        // 61440 B

#define LDFRAGS(buf, so, kb) do {                                              \
    _Pragma("unroll")                                                          \
    for (int mt_ = 0; mt_ < 4; mt_++) {                                        \
        uint32_t a_ = (so) + (uint32_t)(wm0 + mt_*16 + aRow) * PITCHB          \
                    + (kb) + aK;                                               \
        LDSM4(av[buf][mt_][0], av[buf][mt_][1],                                \
              av[buf][mt_][2], av[buf][mt_][3], a_);                           \
    }                                                                          \
    _Pragma("unroll")                                                          \
    for (int jp_ = 0; jp_ < 4; jp_ += 2) {                                     \
        uint32_t b_ = (so) + TILEB                                             \
                    + (uint32_t)(wn0 + jp_*8 + bRow) * PITCHB + (kb) + bK;     \
        LDSM4(bv[buf][jp_][0], bv[buf][jp_][1],                                \
              bv[buf][jp_+1][0], bv[buf][jp_+1][1], b_);                       \
    }                                                                          \
} while(0)

#define DOMMA(buf) do {                                                        \
    _Pragma("unroll")                                                          \
    for (int mt_ = 0; mt_ < 4; mt_++)                                          \
        _Pragma("unroll")                                                      \
        for (int jn_ = 0; jn_ < 4; jn_++)                                      \
            MMA16816(acc[mt_][jn_], av[buf][mt_], bv[buf][jn_]);               \
} while(0)

template<bool UP>
__global__ __launch_bounds__(256, 2) void moe_gemm(
    const __half* __restrict__ Ar, const __half* __restrict__ Br,
    const __half* __restrict__ As, const __half* __restrict__ Bs,
    __half* __restrict__ Chr,
    __half* __restrict__ Chs0, __half* __restrict__ Chs1,
    int NtR, int KR, int NxR, int NtS, int KS)
{
    const int z = blockIdx.z;
    const int NSHZ = UP ? 1 : 2;
    const bool sh = (z < NSHZ);
    const int e = sh ? 0 : (z - NSHZ);
    if (!sh && (int)blockIdx.x >= NxR) return;
    const int m_count = sh ? T_TOK : g_cnt[e];
    const int m0 = blockIdx.y * 128;
    if (m0 >= m_count) return;
    const int n0 = blockIdx.x * 128;
    const int Kloop = sh ? (UP ? KS : (KS >> 1)) : KR;
    const int Krow  = sh ? KS : KR;
    const int koff  = (sh && !UP) ? z * (KS >> 1) : 0;
    const int Nt = sh ? NtS : NtR;

    extern __shared__ __align__(128) char smem[];
    const uint32_t sb = s2u(smem);
    const int tid = threadIdx.x, wid = tid >> 5, lane = tid & 31;

    // ---- loader: thread pair (2t,2t+1) loads 2x16B of row t ----
    const int lrow = tid >> 1;
    const int lelem = (tid & 1) * 16;
    const int gm = m0 + lrow;
    const int idxr = (gm < m_count) ? gm : 0;
    int arow;
    if (sh) {
        arow = idxr;
    } else {
        int s = g_slots[e * MAXS + idxr];
        arow = UP ? (s / TOPK) : s;
    }
    const __half* pA = (sh ? As : Ar) + (size_t)arow * Krow + koff + lelem;
    const __half* pB = (sh ? Bs : (Br + (size_t)e * NtR * KR))
                       + (size_t)(n0 + lrow) * Krow + koff + lelem;
    const uint32_t ldst = (uint32_t)lrow * PITCHB + (uint32_t)(tid & 1) * 32u;

    const int nk = Kloop >> 5;

    auto load_stage = [&](int k) {
        const uint32_t so = sb + (uint32_t)(k % 3) * STGB + ldst;
        const int k0 = k << 5;
        cp16(so,            pA + k0);
        cp16(so + 16,       pA + k0 + 8);
        cp16(so + TILEB,    pB + k0);
        cp16(so + TILEB+16, pB + k0 + 8);
        CP_COMMIT();
    };

    load_stage(0); load_stage(1); load_stage(2);   // nk >= 16 always

    // ---- compute setup ----
    const int wm0 = (wid & 1) * 64;
    const int wn0 = (wid >> 1) * 32;
    const uint32_t aRow = (uint32_t)(lane & 15);
    const uint32_t aK   = (uint32_t)(lane >> 4) * 16u;
    const uint32_t bRow = (uint32_t)((lane & 7) + ((lane >> 4) & 1) * 8);
    const uint32_t bK   = (uint32_t)((lane >> 3) & 1) * 16u;

    float acc[4][4][4];
    #pragma unroll
    for (int i = 0; i < 4; i++)
        #pragma unroll
        for (int j = 0; j < 4; j++)
            #pragma unroll
            for (int q = 0; q < 4; q++) acc[i][j][q] = 0.f;

    uint32_t av[2][4][4], bv[2][4][2];

    asm volatile("cp.async.wait_group 1;" ::: "memory");
    __syncthreads();
    LDFRAGS(0, sb, 0u);

    for (int k = 0; k < nk; k++) {
        const uint32_t so  = sb + (uint32_t)(k % 3) * STGB;
        const uint32_t son = sb + (uint32_t)((k + 1) % 3) * STGB;
        LDFRAGS(1, so, 32u);
        DOMMA(0);
        if (k + 1 < nk) LDFRAGS(0, son, 0u);
        DOMMA(1);
        __syncthreads();
        if (k + 3 < nk) {
            load_stage(k + 3);
            asm volatile("cp.async.wait_group 1;" ::: "memory");
        } else {
            asm volatile("cp.async.wait_group 0;" ::: "memory");
        }
        __syncthreads();
    }

    // ---- epilogue (all fp16 outputs) ----
    const int rw4 = lane >> 2;
    const int cq  = (lane & 3) * 2;
    __half* Cdst;
    if (UP)      Cdst = sh ? Chs0 : Chr;       // Chs0 = g_sh, Chr = g_h
    else if (sh) Cdst = (z == 0) ? Chs0 : Chs1;
    else         Cdst = Chr;                    // g_partial
    #pragma unroll
    for (int mt = 0; mt < 4; mt++) {
        #pragma unroll
        for (int half = 0; half < 2; half++) {
            const int gmi = m0 + wm0 + mt*16 + rw4 + half*8;
            if (gmi >= m_count) continue;
            int crow = gmi; float wsc = 1.f;
            if (!sh) {
                int s = g_slots[e * MAXS + gmi];
                crow = s;
                if (UP) wsc = g_w[s];
            }
            #pragma unroll
            for (int jn = 0; jn < 4; jn++) {
                float v0 = acc[mt][jn][half*2 + 0];
                float v1 = acc[mt][jn][half*2 + 1];
                if (UP) {
                    v0 = v0 > 0.f ? v0 * v0 : 0.f;
                    v1 = v1 > 0.f ? v1 * v1 : 0.f;
                    v0 *= wsc; v1 *= wsc;
                }
                const int col = n0 + wn0 + jn*8 + cq;
                const size_t off = (size_t)crow * Nt + col;
                __half2 hp = __halves2half2(__float2half_rn(v0),
                                            __float2half_rn(v1));
                *(uint32_t*)(Cdst + off) = *(uint32_t*)&hp;
            }
        }
    }
}

// ---------------------------------------------------------------------------
// out[t] = shp0 + shp1 + sum_{k<6} fp16 g_partial[t*6+k]  (all fp16 streams)
// Block 0 re-zeroes g_cnt (globals start zeroed at module load).
__global__ __launch_bounds__(256) void combine_k(float* __restrict__ out) {
    int idx = blockIdx.x * 256 + threadIdx.x;   // float4 index
    int t = idx >> 8;
    int c = idx & 255;
    float4 o;
    {
        uint2 s0 = ((const uint2*)g_shp0)[idx];
        uint2 s1 = ((const uint2*)g_shp1)[idx];
        __half2 a0 = *(__half2*)&s0.x, a1 = *(__half2*)&s0.y;
        __half2 b0 = *(__half2*)&s1.x, b1 = *(__half2*)&s1.y;
        o.x = __low2float(a0) + __low2float(b0);
        o.y = __high2float(a0) + __high2float(b0);
        o.z = __low2float(a1) + __low2float(b1);
        o.w = __high2float(a1) + __high2float(b1);
    }
    #pragma unroll
    for (int k = 0; k < TOPK; k++) {
        uint2 pr = ((const uint2*)g_partial)[(size_t)(t * TOPK + k) * 256 + c];
        __half2 h0 = *(__half2*)&pr.x;
        __half2 h1 = *(__half2*)&pr.y;
        o.x += __low2float(h0);  o.y += __high2float(h0);
        o.z += __low2float(h1);  o.w += __high2float(h1);
    }
    ((float4*)out)[idx] = o;
    if (blockIdx.x == 0 && threadIdx.x < NE) g_cnt[threadIdx.x] = 0;
}

// ---------------------------------------------------------------------------
extern "C" void kernel_launch(void* const* d_in, const int* in_sizes, int n_in,
                              void* d_out, int out_size)
{
    const float* x         = (const float*)d_in[0];
    const float* gate_w    = (const float*)d_in[1];
    const float* e_bias    = (const float*)d_in[2];
    const float* up_w      = (const float*)d_in[3];
    const float* down_w    = (const float*)d_in[4];
    const float* sh_up_w   = (const float*)d_in[5];
    const float* sh_down_w = (const float*)d_in[6];
    float* out = (float*)d_out;

    void *xh, *uw, *dn, *su, *sd, *hb, *shb, *part, *sp0, *sp1;
    cudaGetSymbolAddress(&xh,  g_x);
    cudaGetSymbolAddress(&uw,  g_upw);
    cudaGetSymbolAddress(&dn,  g_dnw);
    cudaGetSymbolAddress(&su,  g_shu);
    cudaGetSymbolAddress(&sd,  g_shd);
    cudaGetSymbolAddress(&hb,  g_h);
    cudaGetSymbolAddress(&shb, g_sh);
    cudaGetSymbolAddress(&part, g_partial);
    cudaGetSymbolAddress(&sp0, g_shp0);
    cudaGetSymbolAddress(&sp1, g_shp1);

    const int smem = (int)SMEM_GEMM;
    cudaFuncSetAttribute(moe_gemm<true>,
                         cudaFuncAttributeMaxDynamicSharedMemorySize, smem);
    cudaFuncSetAttribute(moe_gemm<false>,
                         cudaFuncAttributeMaxDynamicSharedMemorySize, smem);

    // 0: merged converts (all 5 tensors, 8 floats/thread, uint4 stores)
    conv_all_k<<<(CV_OCT + 255) / 256, 256>>>(x, up_w, sh_up_w,
                                              down_w, sh_down_w);
    // 1: router
    router_k<<<T_TOK, 128>>>(x, gate_w, e_bias);

    // 2: UP GEMM — z=0 shared (x<16), z in [1,32] routed (x<4)
    moe_gemm<true><<<dim3(SHI/128, T_TOK/128, NE + 1), 256, smem>>>(
        (const __half*)xh, (const __half*)uw,
        (const __half*)xh, (const __half*)su,
        (__half*)hb, (__half*)shb, nullptr,
        INTER, HID, INTER/128, SHI, HID);

    // 3: DOWN GEMM — z in {0,1} shared K-halves first, z in [2,33] routed;
    //    routed -> fp16 g_partial, shared halves -> fp16 g_shp0/g_shp1
    moe_gemm<false><<<dim3(HID/128, T_TOK/128, NE + 2), 256, smem>>>(
        (const __half*)hb, (const __half*)dn,
        (const __half*)shb, (const __half*)sd,
        (__half*)part, (__half*)sp0, (__half*)sp1,
        HID, INTER, HID/128, HID, SHI);

    // 4: combine (+ re-zero g_cnt)
    combine_k<<<T_TOK, 256>>>(out);
}